// round 7
// baseline (speedup 1.0000x reference)
#include <cuda_runtime.h>
#include <cuda_bf16.h>
#include <cstdint>

#define N_NODES 50000
#define N_EDGES 1600000
#define IN_FEAT 256
#define HIDDEN  128
#define N_CLASSES 16

#define SCAN_CHUNK 256
#define N_SCAN_BLOCKS ((N_NODES + SCAN_CHUNK - 1) / SCAN_CHUNK)   // 196

// ---------------- scratch (device globals; no allocation allowed) ----------------
__device__ int   g_is64;
__device__ int   g_cnt[N_NODES];
__device__ int   g_row_ptr[N_NODES + 1];
__device__ int   g_cursor[N_NODES];
__device__ int   g_col[N_EDGES];
__device__ int   g_block_sums[N_SCAN_BLOCKS];
__device__ int   g_block_off[N_SCAN_BLOCKS];
__device__ float g_dis[N_NODES];
__device__ __align__(16) float g_hs[N_NODES * HIDDEN];     // X@W1 (unscaled)
__device__ __align__(16) float g_a1[N_NODES * HIDDEN];     // relu(agg1 + b1)
__device__ __align__(16) float g_hs2[N_NODES * N_CLASSES]; // (a1@W2) * dis[row]

// ---------------- init: zero counts + edge dtype probe ----------------
__global__ void k_init(const int* __restrict__ ei) {
    int i = blockIdx.x * blockDim.x + threadIdx.x;
    if (i < N_NODES) g_cnt[i] = 0;
    if (i == 0) {
        int is64 = 1;
        for (int j = 1; j < 256; j += 2)
            if (ei[j] != 0) { is64 = 0; break; }
        g_is64 = is64;
    }
}

__device__ __forceinline__ int load_idx(const void* ei, long long pos) {
    if (g_is64) return (int)((const long long*)ei)[pos];
    return ((const int*)ei)[pos];
}

// ---------------- CSR build ----------------
__global__ void k_count(const void* __restrict__ ei) {
    int e = blockIdx.x * blockDim.x + threadIdx.x;
    if (e < N_EDGES) {
        int d = load_idx(ei, (long long)N_EDGES + e);
        if ((unsigned)d < N_NODES) atomicAdd(&g_cnt[d], 1);
    }
}

__global__ __launch_bounds__(SCAN_CHUNK) void k_blocksum() {
    __shared__ int red[SCAN_CHUNK / 32];
    int idx = blockIdx.x * SCAN_CHUNK + threadIdx.x;
    int v = (idx < N_NODES) ? g_cnt[idx] : 0;
#pragma unroll
    for (int o = 16; o > 0; o >>= 1) v += __shfl_down_sync(0xffffffffu, v, o);
    int lane = threadIdx.x & 31, w = threadIdx.x >> 5;
    if (lane == 0) red[w] = v;
    __syncthreads();
    if (threadIdx.x == 0) {
        int s = 0;
#pragma unroll
        for (int i = 0; i < SCAN_CHUNK / 32; i++) s += red[i];
        g_block_sums[blockIdx.x] = s;
    }
}

__global__ __launch_bounds__(256) void k_scan_bs() {
    __shared__ int s[256];
    int t = threadIdx.x;
    s[t] = (t < N_SCAN_BLOCKS) ? g_block_sums[t] : 0;
    __syncthreads();
#pragma unroll
    for (int off = 1; off < 256; off <<= 1) {
        int v = (t >= off) ? s[t - off] : 0;
        __syncthreads();
        s[t] += v;
        __syncthreads();
    }
    if (t < N_SCAN_BLOCKS) g_block_off[t] = s[t];
    if (t == 255) g_row_ptr[N_NODES] = s[255];
}

__global__ __launch_bounds__(SCAN_CHUNK) void k_scan_final() {
    __shared__ int s[SCAN_CHUNK];
    int t = threadIdx.x;
    int idx = blockIdx.x * SCAN_CHUNK + t;
    int c = (idx < N_NODES) ? g_cnt[idx] : 0;
    s[t] = c;
    __syncthreads();
#pragma unroll
    for (int off = 1; off < SCAN_CHUNK; off <<= 1) {
        int v = (t >= off) ? s[t - off] : 0;
        __syncthreads();
        s[t] += v;
        __syncthreads();
    }
    int blockBase = (blockIdx.x == 0) ? 0 : g_block_off[blockIdx.x - 1];
    if (idx < N_NODES) {
        int excl = blockBase + s[t] - c;
        g_row_ptr[idx] = excl;
        g_cursor[idx]  = excl;
        g_dis[idx] = rsqrtf((float)(c + 1));
    }
}

__global__ void k_scatter(const void* __restrict__ ei) {
    int e = blockIdx.x * blockDim.x + threadIdx.x;
    if (e < N_EDGES) {
        int s = load_idx(ei, e);
        int d = load_idx(ei, (long long)N_EDGES + e);
        if ((unsigned)d < N_NODES && (unsigned)s < N_NODES) {
            int p = atomicAdd(&g_cursor[d], 1);
            g_col[p] = s;
        }
    }
}

// ---------------- GEMM1 (tensor core, tf32x3): g_hs = X @ W1 ----------------
// CTA tile 128x128, K staged 16 at a time. 8 warps in 4(M) x 2(N) grid,
// warp tile 32x64 via mma.m16n8k8 (2 M-tiles x 8 N-tiles).
// Accuracy: x = hi + lo (tf32 split); acc += hi*hi + hi*lo + lo*hi  (fp32 acc).
#define BM 128
#define BK 16

__device__ __forceinline__ uint32_t f2tf32(float x) {
    uint32_t u;
    asm("cvt.rna.tf32.f32 %0, %1;" : "=r"(u) : "f"(x));
    return u;
}

__device__ __forceinline__ void mma_tf32(float* c, const uint32_t* a, uint32_t b0, uint32_t b1) {
    asm volatile(
        "mma.sync.aligned.m16n8k8.row.col.f32.tf32.tf32.f32 "
        "{%0,%1,%2,%3}, {%4,%5,%6,%7}, {%8,%9}, {%0,%1,%2,%3};"
        : "+f"(c[0]), "+f"(c[1]), "+f"(c[2]), "+f"(c[3])
        : "r"(a[0]), "r"(a[1]), "r"(a[2]), "r"(a[3]), "r"(b0), "r"(b1));
}

#define AS_STRIDE 20   // 16 k + pad (conflict-free frag reads)
#define BS_STRIDE 136  // 128 n + 8 pad (conflict-free frag reads)

__global__ __launch_bounds__(256) void k_gemm1(const float* __restrict__ X,
                                               const float* __restrict__ W) {
    __shared__ float As[2][BM][AS_STRIDE];   // [hi/lo][m][k]
    __shared__ float Bs[2][BK][BS_STRIDE];   // [hi/lo][k][n]

    const int tid = threadIdx.x;
    const int lane = tid & 31;
    const int wid = tid >> 5;
    const int rowBase = blockIdx.x * BM;

    // warp grid: 4 (M) x 2 (N)
    const int wm = (wid & 3) * 32;
    const int wn = (wid >> 2) * 64;

    // fragment lane decomposition
    const int grp = lane >> 2;   // 0..7
    const int tig = lane & 3;    // 0..3

    // global A loads: 512 float4 over tile (128 rows x 4 f4)
    const int ar0 = tid >> 2,         ac0 = (tid & 3) * 4;
    const int ar1 = (tid + 256) >> 2, ac1 = ((tid + 256) & 3) * 4;
    const bool aok0 = (rowBase + ar0) < N_NODES;
    const bool aok1 = (rowBase + ar1) < N_NODES;
    // global B loads: 512 float4 over tile (16 rows x 32 f4)
    const int br0 = tid >> 5,         bn0 = (tid & 31) * 4;
    const int br1 = (tid + 256) >> 5, bn1 = ((tid + 256) & 31) * 4;

    float acc[2][8][4];
#pragma unroll
    for (int mt = 0; mt < 2; mt++)
#pragma unroll
        for (int nt = 0; nt < 8; nt++)
#pragma unroll
            for (int j = 0; j < 4; j++) acc[mt][nt][j] = 0.f;

    const int NSTAGE = IN_FEAT / BK;  // 16
#pragma unroll 1
    for (int s = 0; s < NSTAGE; s++) {
        const int k0 = s * BK;
        // ---- global loads ----
        float4 a0 = make_float4(0.f, 0.f, 0.f, 0.f);
        float4 a1 = make_float4(0.f, 0.f, 0.f, 0.f);
        if (aok0) a0 = *reinterpret_cast<const float4*>(&X[(size_t)(rowBase + ar0) * IN_FEAT + k0 + ac0]);
        if (aok1) a1 = *reinterpret_cast<const float4*>(&X[(size_t)(rowBase + ar1) * IN_FEAT + k0 + ac1]);
        float4 b0 = *reinterpret_cast<const float4*>(&W[(size_t)(k0 + br0) * HIDDEN + bn0]);
        float4 b1 = *reinterpret_cast<const float4*>(&W[(size_t)(k0 + br1) * HIDDEN + bn1]);

        __syncthreads();  // previous stage's compute done

        // ---- split + store smem ----
        {
            float va[8] = {a0.x, a0.y, a0.z, a0.w, a1.x, a1.y, a1.z, a1.w};
            float hi[8], lo[8];
#pragma unroll
            for (int j = 0; j < 8; j++) {
                uint32_t h = f2tf32(va[j]);
                hi[j] = __uint_as_float(h);
                lo[j] = __uint_as_float(f2tf32(va[j] - hi[j]));
            }
            *reinterpret_cast<float4*>(&As[0][ar0][ac0]) = make_float4(hi[0], hi[1], hi[2], hi[3]);
            *reinterpret_cast<float4*>(&As[1][ar0][ac0]) = make_float4(lo[0], lo[1], lo[2], lo[3]);
            *reinterpret_cast<float4*>(&As[0][ar1][ac1]) = make_float4(hi[4], hi[5], hi[6], hi[7]);
            *reinterpret_cast<float4*>(&As[1][ar1][ac1]) = make_float4(lo[4], lo[5], lo[6], lo[7]);
        }
        {
            float vb[8] = {b0.x, b0.y, b0.z, b0.w, b1.x, b1.y, b1.z, b1.w};
            float hi[8], lo[8];
#pragma unroll
            for (int j = 0; j < 8; j++) {
                uint32_t h = f2tf32(vb[j]);
                hi[j] = __uint_as_float(h);
                lo[j] = __uint_as_float(f2tf32(vb[j] - hi[j]));
            }
            *reinterpret_cast<float4*>(&Bs[0][br0][bn0]) = make_float4(hi[0], hi[1], hi[2], hi[3]);
            *reinterpret_cast<float4*>(&Bs[1][br0][bn0]) = make_float4(lo[0], lo[1], lo[2], lo[3]);
            *reinterpret_cast<float4*>(&Bs[0][br1][bn1]) = make_float4(hi[4], hi[5], hi[6], hi[7]);
            *reinterpret_cast<float4*>(&Bs[1][br1][bn1]) = make_float4(lo[4], lo[5], lo[6], lo[7]);
        }
        __syncthreads();

        // ---- compute: 2 k8 steps ----
#pragma unroll
        for (int ks = 0; ks < BK; ks += 8) {
            uint32_t ah[2][4], al[2][4];
#pragma unroll
            for (int mt = 0; mt < 2; mt++) {
                int r = wm + mt * 16 + grp;
                int c = ks + tig;
                ah[mt][0] = __float_as_uint(As[0][r][c]);
                ah[mt][1] = __float_as_uint(As[0][r + 8][c]);
                ah[mt][2] = __float_as_uint(As[0][r][c + 4]);
                ah[mt][3] = __float_as_uint(As[0][r + 8][c + 4]);
                al[mt][0] = __float_as_uint(As[1][r][c]);
                al[mt][1] = __float_as_uint(As[1][r + 8][c]);
                al[mt][2] = __float_as_uint(As[1][r][c + 4]);
                al[mt][3] = __float_as_uint(As[1][r + 8][c + 4]);
            }
#pragma unroll
            for (int nt = 0; nt < 8; nt++) {
                int n = wn + nt * 8 + grp;
                int c = ks + tig;
                uint32_t bh0 = __float_as_uint(Bs[0][c][n]);
                uint32_t bh1 = __float_as_uint(Bs[0][c + 4][n]);
                uint32_t bl0 = __float_as_uint(Bs[1][c][n]);
                uint32_t bl1 = __float_as_uint(Bs[1][c + 4][n]);
#pragma unroll
                for (int mt = 0; mt < 2; mt++) {
                    mma_tf32(acc[mt][nt], ah[mt], bh0, bh1);   // hi*hi
                    mma_tf32(acc[mt][nt], ah[mt], bl0, bl1);   // hi*lo
                    mma_tf32(acc[mt][nt], al[mt], bh0, bh1);   // lo*hi
                }
            }
        }
    }

    // ---- epilogue: write g_hs ----
#pragma unroll
    for (int mt = 0; mt < 2; mt++) {
#pragma unroll
        for (int nt = 0; nt < 8; nt++) {
            int row0 = rowBase + wm + mt * 16 + grp;
            int col  = wn + nt * 8 + tig * 2;
            if (row0 < N_NODES)
                *reinterpret_cast<float2*>(&g_hs[(size_t)row0 * HIDDEN + col]) =
                    make_float2(acc[mt][nt][0], acc[mt][nt][1]);
            int row1 = row0 + 8;
            if (row1 < N_NODES)
                *reinterpret_cast<float2*>(&g_hs[(size_t)row1 * HIDDEN + col]) =
                    make_float2(acc[mt][nt][2], acc[mt][nt][3]);
        }
    }
}

// ---------------- Agg1: a1 = relu(dis[w]*(h[w]*dis[w] + sum h[s]*dis[s]) + b1) ----------------
__global__ __launch_bounds__(256) void k_agg1(const float* __restrict__ b1) {
    int w = (blockIdx.x * blockDim.x + threadIdx.x) >> 5;
    if (w >= N_NODES) return;
    int lane = threadIdx.x & 31;
    const float4* hs4 = reinterpret_cast<const float4*>(g_hs);

    float dw = g_dis[w];
    float4 self = hs4[(size_t)w * 32 + lane];
    float4 acc0, acc1, acc2, acc3;
    acc0.x = self.x * dw; acc0.y = self.y * dw; acc0.z = self.z * dw; acc0.w = self.w * dw;
    acc1 = make_float4(0.f, 0.f, 0.f, 0.f);
    acc2 = make_float4(0.f, 0.f, 0.f, 0.f);
    acc3 = make_float4(0.f, 0.f, 0.f, 0.f);

    int i = g_row_ptr[w];
    int e = g_row_ptr[w + 1];
    for (; i + 3 < e; i += 4) {
        int s0 = g_col[i], s1 = g_col[i + 1], s2 = g_col[i + 2], s3 = g_col[i + 3];
        float d0 = g_dis[s0], d1 = g_dis[s1], d2 = g_dis[s2], d3 = g_dis[s3];
        float4 v0 = hs4[(size_t)s0 * 32 + lane];
        float4 v1 = hs4[(size_t)s1 * 32 + lane];
        float4 v2 = hs4[(size_t)s2 * 32 + lane];
        float4 v3 = hs4[(size_t)s3 * 32 + lane];
        acc0.x = fmaf(v0.x, d0, acc0.x); acc0.y = fmaf(v0.y, d0, acc0.y);
        acc0.z = fmaf(v0.z, d0, acc0.z); acc0.w = fmaf(v0.w, d0, acc0.w);
        acc1.x = fmaf(v1.x, d1, acc1.x); acc1.y = fmaf(v1.y, d1, acc1.y);
        acc1.z = fmaf(v1.z, d1, acc1.z); acc1.w = fmaf(v1.w, d1, acc1.w);
        acc2.x = fmaf(v2.x, d2, acc2.x); acc2.y = fmaf(v2.y, d2, acc2.y);
        acc2.z = fmaf(v2.z, d2, acc2.z); acc2.w = fmaf(v2.w, d2, acc2.w);
        acc3.x = fmaf(v3.x, d3, acc3.x); acc3.y = fmaf(v3.y, d3, acc3.y);
        acc3.z = fmaf(v3.z, d3, acc3.z); acc3.w = fmaf(v3.w, d3, acc3.w);
    }
    for (; i < e; i++) {
        int s0 = g_col[i];
        float d0 = g_dis[s0];
        float4 v0 = hs4[(size_t)s0 * 32 + lane];
        acc0.x = fmaf(v0.x, d0, acc0.x); acc0.y = fmaf(v0.y, d0, acc0.y);
        acc0.z = fmaf(v0.z, d0, acc0.z); acc0.w = fmaf(v0.w, d0, acc0.w);
    }
    acc0.x += acc1.x + acc2.x + acc3.x;
    acc0.y += acc1.y + acc2.y + acc3.y;
    acc0.z += acc1.z + acc2.z + acc3.z;
    acc0.w += acc1.w + acc2.w + acc3.w;

    float4 b = reinterpret_cast<const float4*>(b1)[lane];
    float4 r;
    r.x = fmaxf(fmaf(dw, acc0.x, b.x), 0.f);
    r.y = fmaxf(fmaf(dw, acc0.y, b.y), 0.f);
    r.z = fmaxf(fmaf(dw, acc0.z, b.z), 0.f);
    r.w = fmaxf(fmaf(dw, acc0.w, b.w), 0.f);
    reinterpret_cast<float4*>(g_a1)[(size_t)w * 32 + lane] = r;
}

// ---------------- GEMM2: hs2 = (a1 @ W2) * dis[row]   [50000x128]x[128x16] ----------------
__global__ __launch_bounds__(256) void k_gemm2(const float* __restrict__ W2) {
    __shared__ float Ws[HIDDEN * N_CLASSES];
    int tid = threadIdx.x;
    for (int i = tid; i < HIDDEN * N_CLASSES; i += 256) Ws[i] = W2[i];
    __syncthreads();
    int idx = blockIdx.x * 256 + tid;
    if (idx >= N_NODES * N_CLASSES) return;
    int n = idx >> 4;
    int c = idx & 15;
    const float* row = &g_a1[(size_t)n * HIDDEN];
    float acc = 0.f;
#pragma unroll
    for (int k = 0; k < HIDDEN; k++) acc = fmaf(row[k], Ws[k * N_CLASSES + c], acc);
    g_hs2[idx] = acc * g_dis[n];
}

// ---------------- Agg2 + bias + softmax ----------------
__global__ __launch_bounds__(256) void k_agg2(const float* __restrict__ b2,
                                              float* __restrict__ out) {
    int w = (blockIdx.x * blockDim.x + threadIdx.x) >> 5;
    int lane = threadIdx.x & 31;
    int n = w * 2 + (lane >> 4);
    int c = lane & 15;
    if (n >= N_NODES) return;

    float acc0 = g_hs2[(size_t)n * N_CLASSES + c];  // self term
    float acc1 = 0.f, acc2 = 0.f, acc3 = 0.f;
    int i = g_row_ptr[n];
    int e = g_row_ptr[n + 1];
    for (; i + 3 < e; i += 4) {
        int s0 = g_col[i], s1 = g_col[i + 1], s2 = g_col[i + 2], s3 = g_col[i + 3];
        acc0 += g_hs2[(size_t)s0 * N_CLASSES + c];
        acc1 += g_hs2[(size_t)s1 * N_CLASSES + c];
        acc2 += g_hs2[(size_t)s2 * N_CLASSES + c];
        acc3 += g_hs2[(size_t)s3 * N_CLASSES + c];
    }
    for (; i < e; i++) acc0 += g_hs2[(size_t)g_col[i] * N_CLASSES + c];
    acc0 += acc1 + acc2 + acc3;

    float logit = fmaf(g_dis[n], acc0, b2[c]);
    out[(size_t)n * N_CLASSES + c] = logit;

    float m = logit;
#pragma unroll
    for (int o = 8; o > 0; o >>= 1) m = fmaxf(m, __shfl_xor_sync(0xffffffffu, m, o, 16));
    float ex = expf(logit - m);
    float sum = ex;
#pragma unroll
    for (int o = 8; o > 0; o >>= 1) sum += __shfl_xor_sync(0xffffffffu, sum, o, 16);
    out[(size_t)N_NODES * N_CLASSES + (size_t)n * N_CLASSES + c] = ex / sum;
}

// ---------------- launch ----------------
extern "C" void kernel_launch(void* const* d_in, const int* in_sizes, int n_in,
                              void* d_out, int out_size) {
    const float* X  = (const float*)d_in[0];
    const void*  EI = d_in[1];
    const float* W1 = (const float*)d_in[2];
    const float* B1 = (const float*)d_in[3];
    const float* W2 = (const float*)d_in[4];
    const float* B2 = (const float*)d_in[5];
    float* out = (float*)d_out;

    k_init<<<(N_NODES + 255) / 256, 256>>>((const int*)EI);           // 0
    k_count<<<(N_EDGES + 255) / 256, 256>>>(EI);                       // 1
    k_blocksum<<<N_SCAN_BLOCKS, SCAN_CHUNK>>>();                       // 2
    k_gemm1<<<(N_NODES + BM - 1) / BM, 256>>>(X, W1);                  // 3 (profiled)
    k_scan_bs<<<1, 256>>>();                                           // 4
    k_scan_final<<<N_SCAN_BLOCKS, SCAN_CHUNK>>>();                     // 5
    k_scatter<<<(N_EDGES + 255) / 256, 256>>>(EI);                     // 6
    k_agg1<<<(N_NODES * 32 + 255) / 256, 256>>>(B1);                   // 7
    k_gemm2<<<(N_NODES * N_CLASSES + 255) / 256, 256>>>(W2);           // 8
    k_agg2<<<(N_NODES * 16 + 255) / 256, 256>>>(B2, out);              // 9
}

// round 8
// speedup vs baseline: 1.0428x; 1.0428x over previous
#include <cuda_runtime.h>
#include <cuda_bf16.h>
#include <cstdint>

#define N_NODES 50000
#define N_EDGES 1600000
#define IN_FEAT 256
#define HIDDEN  128
#define N_CLASSES 16

#define SCAN_CHUNK 256
#define N_SCAN_BLOCKS ((N_NODES + SCAN_CHUNK - 1) / SCAN_CHUNK)   // 196

// ---------------- scratch (device globals; no allocation allowed) ----------------
__device__ int   g_is64;
__device__ int   g_cnt[N_NODES];
__device__ int   g_row_ptr[N_NODES + 1];
__device__ int   g_cursor[N_NODES];
__device__ int   g_col[N_EDGES];
__device__ int   g_block_sums[N_SCAN_BLOCKS];
__device__ int   g_block_off[N_SCAN_BLOCKS];
__device__ float g_dis[N_NODES];
__device__ __align__(16) float g_hs[N_NODES * HIDDEN];     // X@W1 (unscaled)
__device__ __align__(16) float g_a1[N_NODES * HIDDEN];     // relu(agg1 + b1)
__device__ __align__(16) float g_hs2[N_NODES * N_CLASSES]; // (a1@W2) * dis[row]

// ---------------- init: zero counts + edge dtype probe ----------------
__global__ void k_init(const int* __restrict__ ei) {
    int i = blockIdx.x * blockDim.x + threadIdx.x;
    if (i < N_NODES) g_cnt[i] = 0;
    if (i == 0) {
        int is64 = 1;
        for (int j = 1; j < 256; j += 2)
            if (ei[j] != 0) { is64 = 0; break; }
        g_is64 = is64;
    }
}

__device__ __forceinline__ int load_idx(const void* ei, long long pos) {
    if (g_is64) return (int)((const long long*)ei)[pos];
    return ((const int*)ei)[pos];
}

// ---------------- CSR build ----------------
__global__ void k_count(const void* __restrict__ ei) {
    int e = blockIdx.x * blockDim.x + threadIdx.x;
    if (e < N_EDGES) {
        int d = load_idx(ei, (long long)N_EDGES + e);
        if ((unsigned)d < N_NODES) atomicAdd(&g_cnt[d], 1);
    }
}

__global__ __launch_bounds__(SCAN_CHUNK) void k_blocksum() {
    __shared__ int red[SCAN_CHUNK / 32];
    int idx = blockIdx.x * SCAN_CHUNK + threadIdx.x;
    int v = (idx < N_NODES) ? g_cnt[idx] : 0;
#pragma unroll
    for (int o = 16; o > 0; o >>= 1) v += __shfl_down_sync(0xffffffffu, v, o);
    int lane = threadIdx.x & 31, w = threadIdx.x >> 5;
    if (lane == 0) red[w] = v;
    __syncthreads();
    if (threadIdx.x == 0) {
        int s = 0;
#pragma unroll
        for (int i = 0; i < SCAN_CHUNK / 32; i++) s += red[i];
        g_block_sums[blockIdx.x] = s;
    }
}

__global__ __launch_bounds__(256) void k_scan_bs() {
    __shared__ int s[256];
    int t = threadIdx.x;
    s[t] = (t < N_SCAN_BLOCKS) ? g_block_sums[t] : 0;
    __syncthreads();
#pragma unroll
    for (int off = 1; off < 256; off <<= 1) {
        int v = (t >= off) ? s[t - off] : 0;
        __syncthreads();
        s[t] += v;
        __syncthreads();
    }
    if (t < N_SCAN_BLOCKS) g_block_off[t] = s[t];
    if (t == 255) g_row_ptr[N_NODES] = s[255];
}

__global__ __launch_bounds__(SCAN_CHUNK) void k_scan_final() {
    __shared__ int s[SCAN_CHUNK];
    int t = threadIdx.x;
    int idx = blockIdx.x * SCAN_CHUNK + t;
    int c = (idx < N_NODES) ? g_cnt[idx] : 0;
    s[t] = c;
    __syncthreads();
#pragma unroll
    for (int off = 1; off < SCAN_CHUNK; off <<= 1) {
        int v = (t >= off) ? s[t - off] : 0;
        __syncthreads();
        s[t] += v;
        __syncthreads();
    }
    int blockBase = (blockIdx.x == 0) ? 0 : g_block_off[blockIdx.x - 1];
    if (idx < N_NODES) {
        int excl = blockBase + s[t] - c;
        g_row_ptr[idx] = excl;
        g_cursor[idx]  = excl;
        g_dis[idx] = rsqrtf((float)(c + 1));
    }
}

__global__ void k_scatter(const void* __restrict__ ei) {
    int e = blockIdx.x * blockDim.x + threadIdx.x;
    if (e < N_EDGES) {
        int s = load_idx(ei, e);
        int d = load_idx(ei, (long long)N_EDGES + e);
        if ((unsigned)d < N_NODES && (unsigned)s < N_NODES) {
            int p = atomicAdd(&g_cursor[d], 1);
            g_col[p] = s;
        }
    }
}

// ---------------- GEMM1 (tensor core, tf32x3): g_hs = X @ W1 ----------------
// CTA tile 128x128, K staged 16 at a time. 8 warps in 4(M) x 2(N) grid,
// warp tile 32x64 via mma.m16n8k8 (2 M-tiles x 8 N-tiles).
// Accuracy: x = hi + lo (tf32 split); acc += hi*hi + hi*lo + lo*hi  (fp32 acc).
// Pipelining: global loads for stage s+1 are in flight WHILE stage s computes.
#define BM 128
#define BK 16

__device__ __forceinline__ uint32_t f2tf32(float x) {
    uint32_t u;
    asm("cvt.rna.tf32.f32 %0, %1;" : "=r"(u) : "f"(x));
    return u;
}

__device__ __forceinline__ void mma_tf32(float* c, const uint32_t* a, uint32_t b0, uint32_t b1) {
    asm volatile(
        "mma.sync.aligned.m16n8k8.row.col.f32.tf32.tf32.f32 "
        "{%0,%1,%2,%3}, {%4,%5,%6,%7}, {%8,%9}, {%0,%1,%2,%3};"
        : "+f"(c[0]), "+f"(c[1]), "+f"(c[2]), "+f"(c[3])
        : "r"(a[0]), "r"(a[1]), "r"(a[2]), "r"(a[3]), "r"(b0), "r"(b1));
}

#define AS_STRIDE 20   // 16 k + pad (conflict-free frag reads)
#define BS_STRIDE 136  // 128 n + 8 pad (conflict-free frag reads)

__global__ __launch_bounds__(256) void k_gemm1(const float* __restrict__ X,
                                               const float* __restrict__ W) {
    __shared__ float As[2][BM][AS_STRIDE];   // [hi/lo][m][k]
    __shared__ float Bs[2][BK][BS_STRIDE];   // [hi/lo][k][n]

    const int tid = threadIdx.x;
    const int lane = tid & 31;
    const int wid = tid >> 5;
    const int rowBase = blockIdx.x * BM;

    // warp grid: 4 (M) x 2 (N)
    const int wm = (wid & 3) * 32;
    const int wn = (wid >> 2) * 64;

    // fragment lane decomposition
    const int grp = lane >> 2;   // 0..7
    const int tig = lane & 3;    // 0..3

    // global A loads: 512 float4 over tile (128 rows x 4 f4)
    const int ar0 = tid >> 2,         ac0 = (tid & 3) * 4;
    const int ar1 = (tid + 256) >> 2, ac1 = ((tid + 256) & 3) * 4;
    const bool aok0 = (rowBase + ar0) < N_NODES;
    const bool aok1 = (rowBase + ar1) < N_NODES;
    // global B loads: 512 float4 over tile (16 rows x 32 f4)
    const int br0 = tid >> 5,         bn0 = (tid & 31) * 4;
    const int br1 = (tid + 256) >> 5, bn1 = ((tid + 256) & 31) * 4;

    float4 a0, a1, b0, b1;   // staging registers (next stage in flight)

    auto loadG = [&](int k0) {
        a0 = make_float4(0.f, 0.f, 0.f, 0.f);
        a1 = make_float4(0.f, 0.f, 0.f, 0.f);
        if (aok0) a0 = *reinterpret_cast<const float4*>(&X[(size_t)(rowBase + ar0) * IN_FEAT + k0 + ac0]);
        if (aok1) a1 = *reinterpret_cast<const float4*>(&X[(size_t)(rowBase + ar1) * IN_FEAT + k0 + ac1]);
        b0 = *reinterpret_cast<const float4*>(&W[(size_t)(k0 + br0) * HIDDEN + bn0]);
        b1 = *reinterpret_cast<const float4*>(&W[(size_t)(k0 + br1) * HIDDEN + bn1]);
    };

    auto storeS = [&]() {
        {
            float va[8] = {a0.x, a0.y, a0.z, a0.w, a1.x, a1.y, a1.z, a1.w};
            float hi[8], lo[8];
#pragma unroll
            for (int j = 0; j < 8; j++) {
                uint32_t h = f2tf32(va[j]);
                hi[j] = __uint_as_float(h);
                lo[j] = __uint_as_float(f2tf32(va[j] - hi[j]));
            }
            *reinterpret_cast<float4*>(&As[0][ar0][ac0]) = make_float4(hi[0], hi[1], hi[2], hi[3]);
            *reinterpret_cast<float4*>(&As[1][ar0][ac0]) = make_float4(lo[0], lo[1], lo[2], lo[3]);
            *reinterpret_cast<float4*>(&As[0][ar1][ac1]) = make_float4(hi[4], hi[5], hi[6], hi[7]);
            *reinterpret_cast<float4*>(&As[1][ar1][ac1]) = make_float4(lo[4], lo[5], lo[6], lo[7]);
        }
        {
            float vb[8] = {b0.x, b0.y, b0.z, b0.w, b1.x, b1.y, b1.z, b1.w};
            float hi[8], lo[8];
#pragma unroll
            for (int j = 0; j < 8; j++) {
                uint32_t h = f2tf32(vb[j]);
                hi[j] = __uint_as_float(h);
                lo[j] = __uint_as_float(f2tf32(vb[j] - hi[j]));
            }
            *reinterpret_cast<float4*>(&Bs[0][br0][bn0]) = make_float4(hi[0], hi[1], hi[2], hi[3]);
            *reinterpret_cast<float4*>(&Bs[1][br0][bn0]) = make_float4(lo[0], lo[1], lo[2], lo[3]);
            *reinterpret_cast<float4*>(&Bs[0][br1][bn1]) = make_float4(hi[4], hi[5], hi[6], hi[7]);
            *reinterpret_cast<float4*>(&Bs[1][br1][bn1]) = make_float4(lo[4], lo[5], lo[6], lo[7]);
        }
    };

    float acc[2][8][4];
#pragma unroll
    for (int mt = 0; mt < 2; mt++)
#pragma unroll
        for (int nt = 0; nt < 8; nt++)
#pragma unroll
            for (int j = 0; j < 4; j++) acc[mt][nt][j] = 0.f;

    // prologue: stage 0 into smem
    loadG(0);
    storeS();
    __syncthreads();

    const int NSTAGE = IN_FEAT / BK;  // 16
#pragma unroll 1
    for (int s = 0; s < NSTAGE; s++) {
        if (s + 1 < NSTAGE) loadG((s + 1) * BK);   // in flight during compute

        // ---- compute stage s: 2 k8 steps ----
#pragma unroll
        for (int ks = 0; ks < BK; ks += 8) {
            uint32_t ah[2][4], al[2][4];
#pragma unroll
            for (int mt = 0; mt < 2; mt++) {
                int r = wm + mt * 16 + grp;
                int c = ks + tig;
                ah[mt][0] = __float_as_uint(As[0][r][c]);
                ah[mt][1] = __float_as_uint(As[0][r + 8][c]);
                ah[mt][2] = __float_as_uint(As[0][r][c + 4]);
                ah[mt][3] = __float_as_uint(As[0][r + 8][c + 4]);
                al[mt][0] = __float_as_uint(As[1][r][c]);
                al[mt][1] = __float_as_uint(As[1][r + 8][c]);
                al[mt][2] = __float_as_uint(As[1][r][c + 4]);
                al[mt][3] = __float_as_uint(As[1][r + 8][c + 4]);
            }
#pragma unroll
            for (int nt = 0; nt < 8; nt++) {
                int n = wn + nt * 8 + grp;
                int c = ks + tig;
                uint32_t bh0 = __float_as_uint(Bs[0][c][n]);
                uint32_t bh1 = __float_as_uint(Bs[0][c + 4][n]);
                uint32_t bl0 = __float_as_uint(Bs[1][c][n]);
                uint32_t bl1 = __float_as_uint(Bs[1][c + 4][n]);
#pragma unroll
                for (int mt = 0; mt < 2; mt++) {
                    mma_tf32(acc[mt][nt], ah[mt], bh0, bh1);   // hi*hi
                    mma_tf32(acc[mt][nt], ah[mt], bl0, bl1);   // hi*lo
                    mma_tf32(acc[mt][nt], al[mt], bh0, bh1);   // lo*hi
                }
            }
        }

        if (s + 1 < NSTAGE) {
            __syncthreads();   // all warps done reading smem
            storeS();          // commit prefetched stage
            __syncthreads();
        }
    }

    // ---- epilogue: write g_hs ----
#pragma unroll
    for (int mt = 0; mt < 2; mt++) {
#pragma unroll
        for (int nt = 0; nt < 8; nt++) {
            int row0 = rowBase + wm + mt * 16 + grp;
            int col  = wn + nt * 8 + tig * 2;
            if (row0 < N_NODES)
                *reinterpret_cast<float2*>(&g_hs[(size_t)row0 * HIDDEN + col]) =
                    make_float2(acc[mt][nt][0], acc[mt][nt][1]);
            int row1 = row0 + 8;
            if (row1 < N_NODES)
                *reinterpret_cast<float2*>(&g_hs[(size_t)row1 * HIDDEN + col]) =
                    make_float2(acc[mt][nt][2], acc[mt][nt][3]);
        }
    }
}

// ---------------- Agg1: a1 = relu(dis[w]*(h[w]*dis[w] + sum h[s]*dis[s]) + b1) ----------------
// one warp per node; 8-wide unrolled gather for MLP
__global__ __launch_bounds__(256) void k_agg1(const float* __restrict__ b1) {
    int w = (blockIdx.x * blockDim.x + threadIdx.x) >> 5;
    if (w >= N_NODES) return;
    int lane = threadIdx.x & 31;
    const float4* hs4 = reinterpret_cast<const float4*>(g_hs);

    float dw = g_dis[w];
    float4 self = hs4[(size_t)w * 32 + lane];
    float4 acc0, acc1, acc2, acc3;
    acc0.x = self.x * dw; acc0.y = self.y * dw; acc0.z = self.z * dw; acc0.w = self.w * dw;
    acc1 = make_float4(0.f, 0.f, 0.f, 0.f);
    acc2 = make_float4(0.f, 0.f, 0.f, 0.f);
    acc3 = make_float4(0.f, 0.f, 0.f, 0.f);

    int i = g_row_ptr[w];
    int e = g_row_ptr[w + 1];
    for (; i + 7 < e; i += 8) {
        int s0 = g_col[i],     s1 = g_col[i + 1], s2 = g_col[i + 2], s3 = g_col[i + 3];
        int s4 = g_col[i + 4], s5 = g_col[i + 5], s6 = g_col[i + 6], s7 = g_col[i + 7];
        float d0 = g_dis[s0], d1 = g_dis[s1], d2 = g_dis[s2], d3 = g_dis[s3];
        float d4 = g_dis[s4], d5 = g_dis[s5], d6 = g_dis[s6], d7 = g_dis[s7];
        float4 v0 = hs4[(size_t)s0 * 32 + lane];
        float4 v1 = hs4[(size_t)s1 * 32 + lane];
        float4 v2 = hs4[(size_t)s2 * 32 + lane];
        float4 v3 = hs4[(size_t)s3 * 32 + lane];
        float4 v4 = hs4[(size_t)s4 * 32 + lane];
        float4 v5 = hs4[(size_t)s5 * 32 + lane];
        float4 v6 = hs4[(size_t)s6 * 32 + lane];
        float4 v7 = hs4[(size_t)s7 * 32 + lane];
        acc0.x = fmaf(v0.x, d0, acc0.x); acc0.y = fmaf(v0.y, d0, acc0.y);
        acc0.z = fmaf(v0.z, d0, acc0.z); acc0.w = fmaf(v0.w, d0, acc0.w);
        acc1.x = fmaf(v1.x, d1, acc1.x); acc1.y = fmaf(v1.y, d1, acc1.y);
        acc1.z = fmaf(v1.z, d1, acc1.z); acc1.w = fmaf(v1.w, d1, acc1.w);
        acc2.x = fmaf(v2.x, d2, acc2.x); acc2.y = fmaf(v2.y, d2, acc2.y);
        acc2.z = fmaf(v2.z, d2, acc2.z); acc2.w = fmaf(v2.w, d2, acc2.w);
        acc3.x = fmaf(v3.x, d3, acc3.x); acc3.y = fmaf(v3.y, d3, acc3.y);
        acc3.z = fmaf(v3.z, d3, acc3.z); acc3.w = fmaf(v3.w, d3, acc3.w);
        acc0.x = fmaf(v4.x, d4, acc0.x); acc0.y = fmaf(v4.y, d4, acc0.y);
        acc0.z = fmaf(v4.z, d4, acc0.z); acc0.w = fmaf(v4.w, d4, acc0.w);
        acc1.x = fmaf(v5.x, d5, acc1.x); acc1.y = fmaf(v5.y, d5, acc1.y);
        acc1.z = fmaf(v5.z, d5, acc1.z); acc1.w = fmaf(v5.w, d5, acc1.w);
        acc2.x = fmaf(v6.x, d6, acc2.x); acc2.y = fmaf(v6.y, d6, acc2.y);
        acc2.z = fmaf(v6.z, d6, acc2.z); acc2.w = fmaf(v6.w, d6, acc2.w);
        acc3.x = fmaf(v7.x, d7, acc3.x); acc3.y = fmaf(v7.y, d7, acc3.y);
        acc3.z = fmaf(v7.z, d7, acc3.z); acc3.w = fmaf(v7.w, d7, acc3.w);
    }
    for (; i + 3 < e; i += 4) {
        int s0 = g_col[i], s1 = g_col[i + 1], s2 = g_col[i + 2], s3 = g_col[i + 3];
        float d0 = g_dis[s0], d1 = g_dis[s1], d2 = g_dis[s2], d3 = g_dis[s3];
        float4 v0 = hs4[(size_t)s0 * 32 + lane];
        float4 v1 = hs4[(size_t)s1 * 32 + lane];
        float4 v2 = hs4[(size_t)s2 * 32 + lane];
        float4 v3 = hs4[(size_t)s3 * 32 + lane];
        acc0.x = fmaf(v0.x, d0, acc0.x); acc0.y = fmaf(v0.y, d0, acc0.y);
        acc0.z = fmaf(v0.z, d0, acc0.z); acc0.w = fmaf(v0.w, d0, acc0.w);
        acc1.x = fmaf(v1.x, d1, acc1.x); acc1.y = fmaf(v1.y, d1, acc1.y);
        acc1.z = fmaf(v1.z, d1, acc1.z); acc1.w = fmaf(v1.w, d1, acc1.w);
        acc2.x = fmaf(v2.x, d2, acc2.x); acc2.y = fmaf(v2.y, d2, acc2.y);
        acc2.z = fmaf(v2.z, d2, acc2.z); acc2.w = fmaf(v2.w, d2, acc2.w);
        acc3.x = fmaf(v3.x, d3, acc3.x); acc3.y = fmaf(v3.y, d3, acc3.y);
        acc3.z = fmaf(v3.z, d3, acc3.z); acc3.w = fmaf(v3.w, d3, acc3.w);
    }
    for (; i < e; i++) {
        int s0 = g_col[i];
        float d0 = g_dis[s0];
        float4 v0 = hs4[(size_t)s0 * 32 + lane];
        acc0.x = fmaf(v0.x, d0, acc0.x); acc0.y = fmaf(v0.y, d0, acc0.y);
        acc0.z = fmaf(v0.z, d0, acc0.z); acc0.w = fmaf(v0.w, d0, acc0.w);
    }
    acc0.x += acc1.x + acc2.x + acc3.x;
    acc0.y += acc1.y + acc2.y + acc3.y;
    acc0.z += acc1.z + acc2.z + acc3.z;
    acc0.w += acc1.w + acc2.w + acc3.w;

    float4 b = reinterpret_cast<const float4*>(b1)[lane];
    float4 r;
    r.x = fmaxf(fmaf(dw, acc0.x, b.x), 0.f);
    r.y = fmaxf(fmaf(dw, acc0.y, b.y), 0.f);
    r.z = fmaxf(fmaf(dw, acc0.z, b.z), 0.f);
    r.w = fmaxf(fmaf(dw, acc0.w, b.w), 0.f);
    reinterpret_cast<float4*>(g_a1)[(size_t)w * 32 + lane] = r;
}

// ---------------- GEMM2: hs2 = (a1 @ W2) * dis[row]   [50000x128]x[128x16] ----------------
__global__ __launch_bounds__(256) void k_gemm2(const float* __restrict__ W2) {
    __shared__ float Ws[HIDDEN * N_CLASSES];
    int tid = threadIdx.x;
    for (int i = tid; i < HIDDEN * N_CLASSES; i += 256) Ws[i] = W2[i];
    __syncthreads();
    int idx = blockIdx.x * 256 + tid;
    if (idx >= N_NODES * N_CLASSES) return;
    int n = idx >> 4;
    int c = idx & 15;
    const float* row = &g_a1[(size_t)n * HIDDEN];
    float acc = 0.f;
#pragma unroll
    for (int k = 0; k < HIDDEN; k++) acc = fmaf(row[k], Ws[k * N_CLASSES + c], acc);
    g_hs2[idx] = acc * g_dis[n];
}

// ---------------- Agg2 + bias + softmax ----------------
__global__ __launch_bounds__(256) void k_agg2(const float* __restrict__ b2,
                                              float* __restrict__ out) {
    int w = (blockIdx.x * blockDim.x + threadIdx.x) >> 5;
    int lane = threadIdx.x & 31;
    int n = w * 2 + (lane >> 4);
    int c = lane & 15;
    if (n >= N_NODES) return;

    float acc0 = g_hs2[(size_t)n * N_CLASSES + c];  // self term
    float acc1 = 0.f, acc2 = 0.f, acc3 = 0.f;
    int i = g_row_ptr[n];
    int e = g_row_ptr[n + 1];
    for (; i + 3 < e; i += 4) {
        int s0 = g_col[i], s1 = g_col[i + 1], s2 = g_col[i + 2], s3 = g_col[i + 3];
        acc0 += g_hs2[(size_t)s0 * N_CLASSES + c];
        acc1 += g_hs2[(size_t)s1 * N_CLASSES + c];
        acc2 += g_hs2[(size_t)s2 * N_CLASSES + c];
        acc3 += g_hs2[(size_t)s3 * N_CLASSES + c];
    }
    for (; i < e; i++) acc0 += g_hs2[(size_t)g_col[i] * N_CLASSES + c];
    acc0 += acc1 + acc2 + acc3;

    float logit = fmaf(g_dis[n], acc0, b2[c]);
    out[(size_t)n * N_CLASSES + c] = logit;

    float m = logit;
#pragma unroll
    for (int o = 8; o > 0; o >>= 1) m = fmaxf(m, __shfl_xor_sync(0xffffffffu, m, o, 16));
    float ex = expf(logit - m);
    float sum = ex;
#pragma unroll
    for (int o = 8; o > 0; o >>= 1) sum += __shfl_xor_sync(0xffffffffu, sum, o, 16);
    out[(size_t)N_NODES * N_CLASSES + (size_t)n * N_CLASSES + c] = ex / sum;
}

// ---------------- launch ----------------
extern "C" void kernel_launch(void* const* d_in, const int* in_sizes, int n_in,
                              void* d_out, int out_size) {
    const float* X  = (const float*)d_in[0];
    const void*  EI = d_in[1];
    const float* W1 = (const float*)d_in[2];
    const float* B1 = (const float*)d_in[3];
    const float* W2 = (const float*)d_in[4];
    const float* B2 = (const float*)d_in[5];
    float* out = (float*)d_out;

    k_init<<<(N_NODES + 255) / 256, 256>>>((const int*)EI);           // 0
    k_count<<<(N_EDGES + 255) / 256, 256>>>(EI);                       // 1
    k_blocksum<<<N_SCAN_BLOCKS, SCAN_CHUNK>>>();                       // 2
    k_gemm1<<<(N_NODES + BM - 1) / BM, 256>>>(X, W1);                  // 3 (profiled)
    k_scan_bs<<<1, 256>>>();                                           // 4
    k_scan_final<<<N_SCAN_BLOCKS, SCAN_CHUNK>>>();                     // 5
    k_scatter<<<(N_EDGES + 255) / 256, 256>>>(EI);                     // 6
    k_agg1<<<(N_NODES * 32 + 255) / 256, 256>>>(B1);                   // 7
    k_gemm2<<<(N_NODES * N_CLASSES + 255) / 256, 256>>>(W2);           // 8
    k_agg2<<<(N_NODES * 16 + 255) / 256, 256>>>(B2, out);              // 9
}

// round 9
// speedup vs baseline: 1.2525x; 1.2010x over previous
#include <cuda_runtime.h>
#include <cuda_fp16.h>
#include <cstdint>

#define N_NODES 50000
#define N_EDGES 1600000
#define IN_FEAT 256
#define HIDDEN  128
#define N_CLASSES 16

#define SCAN_CHUNK 256
#define N_SCAN_BLOCKS ((N_NODES + SCAN_CHUNK - 1) / SCAN_CHUNK)   // 196

// ---------------- scratch (device globals; no allocation allowed) ----------------
__device__ int   g_is64;
__device__ int   g_cnt[N_NODES];
__device__ int   g_row_ptr[N_NODES + 1];
__device__ int   g_cursor[N_NODES];
__device__ int   g_col[N_EDGES];
__device__ int   g_block_sums[N_SCAN_BLOCKS];
__device__ int   g_block_off[N_SCAN_BLOCKS];
__device__ float g_dis[N_NODES];
__device__ __align__(16) __half g_hsh[N_NODES * HIDDEN];   // X@W1 (unscaled), fp16
__device__ __align__(16) float g_a1[N_NODES * HIDDEN];     // relu(agg1 + b1)
__device__ __align__(16) float g_hs2[N_NODES * N_CLASSES]; // (a1@W2) * dis[row]

struct __align__(8) half4 { __half2 a, b; };

// ---------------- init: zero counts + edge dtype probe ----------------
__global__ void k_init(const int* __restrict__ ei) {
    int i = blockIdx.x * blockDim.x + threadIdx.x;
    if (i < N_NODES) g_cnt[i] = 0;
    if (i == 0) {
        int is64 = 1;
        for (int j = 1; j < 256; j += 2)
            if (ei[j] != 0) { is64 = 0; break; }
        g_is64 = is64;
    }
}

__device__ __forceinline__ int load_idx(const void* ei, long long pos) {
    if (g_is64) return (int)((const long long*)ei)[pos];
    return ((const int*)ei)[pos];
}

// ---------------- CSR build ----------------
__global__ void k_count(const void* __restrict__ ei) {
    int e = blockIdx.x * blockDim.x + threadIdx.x;
    if (e < N_EDGES) {
        int d = load_idx(ei, (long long)N_EDGES + e);
        if ((unsigned)d < N_NODES) atomicAdd(&g_cnt[d], 1);
    }
}

__global__ __launch_bounds__(SCAN_CHUNK) void k_blocksum() {
    __shared__ int red[SCAN_CHUNK / 32];
    int idx = blockIdx.x * SCAN_CHUNK + threadIdx.x;
    int v = (idx < N_NODES) ? g_cnt[idx] : 0;
#pragma unroll
    for (int o = 16; o > 0; o >>= 1) v += __shfl_down_sync(0xffffffffu, v, o);
    int lane = threadIdx.x & 31, w = threadIdx.x >> 5;
    if (lane == 0) red[w] = v;
    __syncthreads();
    if (threadIdx.x == 0) {
        int s = 0;
#pragma unroll
        for (int i = 0; i < SCAN_CHUNK / 32; i++) s += red[i];
        g_block_sums[blockIdx.x] = s;
    }
}

__global__ __launch_bounds__(256) void k_scan_bs() {
    __shared__ int s[256];
    int t = threadIdx.x;
    s[t] = (t < N_SCAN_BLOCKS) ? g_block_sums[t] : 0;
    __syncthreads();
#pragma unroll
    for (int off = 1; off < 256; off <<= 1) {
        int v = (t >= off) ? s[t - off] : 0;
        __syncthreads();
        s[t] += v;
        __syncthreads();
    }
    if (t < N_SCAN_BLOCKS) g_block_off[t] = s[t];
    if (t == 255) g_row_ptr[N_NODES] = s[255];
}

__global__ __launch_bounds__(SCAN_CHUNK) void k_scan_final() {
    __shared__ int s[SCAN_CHUNK];
    int t = threadIdx.x;
    int idx = blockIdx.x * SCAN_CHUNK + t;
    int c = (idx < N_NODES) ? g_cnt[idx] : 0;
    s[t] = c;
    __syncthreads();
#pragma unroll
    for (int off = 1; off < SCAN_CHUNK; off <<= 1) {
        int v = (t >= off) ? s[t - off] : 0;
        __syncthreads();
        s[t] += v;
        __syncthreads();
    }
    int blockBase = (blockIdx.x == 0) ? 0 : g_block_off[blockIdx.x - 1];
    if (idx < N_NODES) {
        int excl = blockBase + s[t] - c;
        g_row_ptr[idx] = excl;
        g_cursor[idx]  = excl;
        g_dis[idx] = rsqrtf((float)(c + 1));
    }
}

__global__ void k_scatter(const void* __restrict__ ei) {
    int e = blockIdx.x * blockDim.x + threadIdx.x;
    if (e < N_EDGES) {
        int s = load_idx(ei, e);
        int d = load_idx(ei, (long long)N_EDGES + e);
        if ((unsigned)d < N_NODES && (unsigned)s < N_NODES) {
            int p = atomicAdd(&g_cursor[d], 1);
            g_col[p] = s;
        }
    }
}

// ---------------- GEMM1 (tensor core, tf32x2): g_hsh = fp16(X @ W1) ----------------
// CTA 128x128, K in 16-wide stages. 8 warps 4(M)x2(N), warp tile 32x64 (m16n8k8).
// Split A only: acc += a_hi*b + a_lo*b  (b = single-rounded tf32, fp32 acc).
#define BM 128
#define BK 16

__device__ __forceinline__ uint32_t f2tf32(float x) {
    uint32_t u;
    asm("cvt.rna.tf32.f32 %0, %1;" : "=r"(u) : "f"(x));
    return u;
}

__device__ __forceinline__ void mma_tf32(float* c, const uint32_t* a, uint32_t b0, uint32_t b1) {
    asm volatile(
        "mma.sync.aligned.m16n8k8.row.col.f32.tf32.tf32.f32 "
        "{%0,%1,%2,%3}, {%4,%5,%6,%7}, {%8,%9}, {%0,%1,%2,%3};"
        : "+f"(c[0]), "+f"(c[1]), "+f"(c[2]), "+f"(c[3])
        : "r"(a[0]), "r"(a[1]), "r"(a[2]), "r"(a[3]), "r"(b0), "r"(b1));
}

#define AS_STRIDE 20   // 16 k + pad (conflict-free)
#define BS_STRIDE 136  // 128 n + 8 pad (conflict-free)

__global__ __launch_bounds__(256, 2) void k_gemm1(const float* __restrict__ X,
                                                  const float* __restrict__ W) {
    __shared__ float As[2][BM][AS_STRIDE];   // [hi/lo][m][k]
    __shared__ float Bs[BK][BS_STRIDE];      // [k][n] (hi only)

    const int tid = threadIdx.x;
    const int lane = tid & 31;
    const int wid = tid >> 5;
    const int rowBase = blockIdx.x * BM;

    const int wm = (wid & 3) * 32;
    const int wn = (wid >> 2) * 64;
    const int grp = lane >> 2;
    const int tig = lane & 3;

    const int ar0 = tid >> 2,         ac0 = (tid & 3) * 4;
    const int ar1 = (tid + 256) >> 2, ac1 = ((tid + 256) & 3) * 4;
    const bool aok0 = (rowBase + ar0) < N_NODES;
    const bool aok1 = (rowBase + ar1) < N_NODES;
    const int br0 = tid >> 5,         bn0 = (tid & 31) * 4;
    const int br1 = (tid + 256) >> 5, bn1 = ((tid + 256) & 31) * 4;

    float4 a0, a1, b0, b1;

    auto loadG = [&](int k0) {
        a0 = make_float4(0.f, 0.f, 0.f, 0.f);
        a1 = make_float4(0.f, 0.f, 0.f, 0.f);
        if (aok0) a0 = *reinterpret_cast<const float4*>(&X[(size_t)(rowBase + ar0) * IN_FEAT + k0 + ac0]);
        if (aok1) a1 = *reinterpret_cast<const float4*>(&X[(size_t)(rowBase + ar1) * IN_FEAT + k0 + ac1]);
        b0 = *reinterpret_cast<const float4*>(&W[(size_t)(k0 + br0) * HIDDEN + bn0]);
        b1 = *reinterpret_cast<const float4*>(&W[(size_t)(k0 + br1) * HIDDEN + bn1]);
    };

    auto storeS = [&]() {
        {
            float va[8] = {a0.x, a0.y, a0.z, a0.w, a1.x, a1.y, a1.z, a1.w};
            float hi[8], lo[8];
#pragma unroll
            for (int j = 0; j < 8; j++) {
                uint32_t h = f2tf32(va[j]);
                hi[j] = __uint_as_float(h);
                lo[j] = __uint_as_float(f2tf32(va[j] - hi[j]));
            }
            *reinterpret_cast<float4*>(&As[0][ar0][ac0]) = make_float4(hi[0], hi[1], hi[2], hi[3]);
            *reinterpret_cast<float4*>(&As[1][ar0][ac0]) = make_float4(lo[0], lo[1], lo[2], lo[3]);
            *reinterpret_cast<float4*>(&As[0][ar1][ac1]) = make_float4(hi[4], hi[5], hi[6], hi[7]);
            *reinterpret_cast<float4*>(&As[1][ar1][ac1]) = make_float4(lo[4], lo[5], lo[6], lo[7]);
        }
        {
            // B: single tf32 rounding (no split)
            float vb[8] = {b0.x, b0.y, b0.z, b0.w, b1.x, b1.y, b1.z, b1.w};
            float h[8];
#pragma unroll
            for (int j = 0; j < 8; j++) h[j] = __uint_as_float(f2tf32(vb[j]));
            *reinterpret_cast<float4*>(&Bs[br0][bn0]) = make_float4(h[0], h[1], h[2], h[3]);
            *reinterpret_cast<float4*>(&Bs[br1][bn1]) = make_float4(h[4], h[5], h[6], h[7]);
        }
    };

    float acc[2][8][4];
#pragma unroll
    for (int mt = 0; mt < 2; mt++)
#pragma unroll
        for (int nt = 0; nt < 8; nt++)
#pragma unroll
            for (int j = 0; j < 4; j++) acc[mt][nt][j] = 0.f;

    loadG(0);
    storeS();
    __syncthreads();

    const int NSTAGE = IN_FEAT / BK;  // 16
#pragma unroll 1
    for (int s = 0; s < NSTAGE; s++) {
        if (s + 1 < NSTAGE) loadG((s + 1) * BK);   // prefetch overlaps compute

#pragma unroll
        for (int ks = 0; ks < BK; ks += 8) {
            uint32_t ah[2][4], al[2][4];
#pragma unroll
            for (int mt = 0; mt < 2; mt++) {
                int r = wm + mt * 16 + grp;
                int c = ks + tig;
                ah[mt][0] = __float_as_uint(As[0][r][c]);
                ah[mt][1] = __float_as_uint(As[0][r + 8][c]);
                ah[mt][2] = __float_as_uint(As[0][r][c + 4]);
                ah[mt][3] = __float_as_uint(As[0][r + 8][c + 4]);
                al[mt][0] = __float_as_uint(As[1][r][c]);
                al[mt][1] = __float_as_uint(As[1][r + 8][c]);
                al[mt][2] = __float_as_uint(As[1][r][c + 4]);
                al[mt][3] = __float_as_uint(As[1][r + 8][c + 4]);
            }
#pragma unroll
            for (int nt = 0; nt < 8; nt++) {
                int n = wn + nt * 8 + grp;
                int c = ks + tig;
                uint32_t bh0 = __float_as_uint(Bs[c][n]);
                uint32_t bh1 = __float_as_uint(Bs[c + 4][n]);
#pragma unroll
                for (int mt = 0; mt < 2; mt++) {
                    mma_tf32(acc[mt][nt], ah[mt], bh0, bh1);   // a_hi * b
                    mma_tf32(acc[mt][nt], al[mt], bh0, bh1);   // a_lo * b
                }
            }
        }

        if (s + 1 < NSTAGE) {
            __syncthreads();
            storeS();
            __syncthreads();
        }
    }

    // ---- epilogue: write g_hsh (fp16) ----
#pragma unroll
    for (int mt = 0; mt < 2; mt++) {
#pragma unroll
        for (int nt = 0; nt < 8; nt++) {
            int row0 = rowBase + wm + mt * 16 + grp;
            int col  = wn + nt * 8 + tig * 2;
            if (row0 < N_NODES)
                *reinterpret_cast<__half2*>(&g_hsh[(size_t)row0 * HIDDEN + col]) =
                    __floats2half2_rn(acc[mt][nt][0], acc[mt][nt][1]);
            int row1 = row0 + 8;
            if (row1 < N_NODES)
                *reinterpret_cast<__half2*>(&g_hsh[(size_t)row1 * HIDDEN + col]) =
                    __floats2half2_rn(acc[mt][nt][2], acc[mt][nt][3]);
        }
    }
}

// ---------------- Agg1: a1 = relu(dis[w]*(h[w]*dis[w] + sum h[s]*dis[s]) + b1) ----------------
// one warp per node; fp16 gather (half the L2 traffic), 8-wide unroll, fp32 accum
__device__ __forceinline__ void acc_h4(float4& acc, half4 v, float d) {
    float2 f0 = __half22float2(v.a);
    float2 f1 = __half22float2(v.b);
    acc.x = fmaf(f0.x, d, acc.x);
    acc.y = fmaf(f0.y, d, acc.y);
    acc.z = fmaf(f1.x, d, acc.z);
    acc.w = fmaf(f1.y, d, acc.w);
}

__global__ __launch_bounds__(256) void k_agg1(const float* __restrict__ b1) {
    int w = (blockIdx.x * blockDim.x + threadIdx.x) >> 5;
    if (w >= N_NODES) return;
    int lane = threadIdx.x & 31;
    const half4* hs4 = reinterpret_cast<const half4*>(g_hsh);

    float dw = g_dis[w];
    float4 acc0 = make_float4(0.f, 0.f, 0.f, 0.f);
    float4 acc1 = acc0, acc2 = acc0, acc3 = acc0;
    acc_h4(acc0, hs4[(size_t)w * 32 + lane], dw);   // self term

    int i = g_row_ptr[w];
    int e = g_row_ptr[w + 1];
    for (; i + 7 < e; i += 8) {
        int s0 = g_col[i],     s1 = g_col[i + 1], s2 = g_col[i + 2], s3 = g_col[i + 3];
        int s4 = g_col[i + 4], s5 = g_col[i + 5], s6 = g_col[i + 6], s7 = g_col[i + 7];
        float d0 = g_dis[s0], d1 = g_dis[s1], d2 = g_dis[s2], d3 = g_dis[s3];
        float d4 = g_dis[s4], d5 = g_dis[s5], d6 = g_dis[s6], d7 = g_dis[s7];
        half4 v0 = hs4[(size_t)s0 * 32 + lane];
        half4 v1 = hs4[(size_t)s1 * 32 + lane];
        half4 v2 = hs4[(size_t)s2 * 32 + lane];
        half4 v3 = hs4[(size_t)s3 * 32 + lane];
        half4 v4 = hs4[(size_t)s4 * 32 + lane];
        half4 v5 = hs4[(size_t)s5 * 32 + lane];
        half4 v6 = hs4[(size_t)s6 * 32 + lane];
        half4 v7 = hs4[(size_t)s7 * 32 + lane];
        acc_h4(acc0, v0, d0); acc_h4(acc1, v1, d1);
        acc_h4(acc2, v2, d2); acc_h4(acc3, v3, d3);
        acc_h4(acc0, v4, d4); acc_h4(acc1, v5, d5);
        acc_h4(acc2, v6, d6); acc_h4(acc3, v7, d7);
    }
    for (; i + 3 < e; i += 4) {
        int s0 = g_col[i], s1 = g_col[i + 1], s2 = g_col[i + 2], s3 = g_col[i + 3];
        float d0 = g_dis[s0], d1 = g_dis[s1], d2 = g_dis[s2], d3 = g_dis[s3];
        half4 v0 = hs4[(size_t)s0 * 32 + lane];
        half4 v1 = hs4[(size_t)s1 * 32 + lane];
        half4 v2 = hs4[(size_t)s2 * 32 + lane];
        half4 v3 = hs4[(size_t)s3 * 32 + lane];
        acc_h4(acc0, v0, d0); acc_h4(acc1, v1, d1);
        acc_h4(acc2, v2, d2); acc_h4(acc3, v3, d3);
    }
    for (; i < e; i++) {
        int s0 = g_col[i];
        acc_h4(acc0, hs4[(size_t)s0 * 32 + lane], g_dis[s0]);
    }
    acc0.x += acc1.x + acc2.x + acc3.x;
    acc0.y += acc1.y + acc2.y + acc3.y;
    acc0.z += acc1.z + acc2.z + acc3.z;
    acc0.w += acc1.w + acc2.w + acc3.w;

    float4 b = reinterpret_cast<const float4*>(b1)[lane];
    float4 r;
    r.x = fmaxf(fmaf(dw, acc0.x, b.x), 0.f);
    r.y = fmaxf(fmaf(dw, acc0.y, b.y), 0.f);
    r.z = fmaxf(fmaf(dw, acc0.z, b.z), 0.f);
    r.w = fmaxf(fmaf(dw, acc0.w, b.w), 0.f);
    reinterpret_cast<float4*>(g_a1)[(size_t)w * 32 + lane] = r;
}

// ---------------- GEMM2: hs2 = (a1 @ W2) * dis[row]   [50000x128]x[128x16] ----------------
__global__ __launch_bounds__(256) void k_gemm2(const float* __restrict__ W2) {
    __shared__ float Ws[HIDDEN * N_CLASSES];
    int tid = threadIdx.x;
    for (int i = tid; i < HIDDEN * N_CLASSES; i += 256) Ws[i] = W2[i];
    __syncthreads();
    int idx = blockIdx.x * 256 + tid;
    if (idx >= N_NODES * N_CLASSES) return;
    int n = idx >> 4;
    int c = idx & 15;
    const float* row = &g_a1[(size_t)n * HIDDEN];
    float acc = 0.f;
#pragma unroll
    for (int k = 0; k < HIDDEN; k++) acc = fmaf(row[k], Ws[k * N_CLASSES + c], acc);
    g_hs2[idx] = acc * g_dis[n];
}

// ---------------- Agg2 + bias + softmax ----------------
__global__ __launch_bounds__(256) void k_agg2(const float* __restrict__ b2,
                                              float* __restrict__ out) {
    int w = (blockIdx.x * blockDim.x + threadIdx.x) >> 5;
    int lane = threadIdx.x & 31;
    int n = w * 2 + (lane >> 4);
    int c = lane & 15;
    if (n >= N_NODES) return;

    float acc0 = g_hs2[(size_t)n * N_CLASSES + c];  // self term
    float acc1 = 0.f, acc2 = 0.f, acc3 = 0.f;
    int i = g_row_ptr[n];
    int e = g_row_ptr[n + 1];
    for (; i + 3 < e; i += 4) {
        int s0 = g_col[i], s1 = g_col[i + 1], s2 = g_col[i + 2], s3 = g_col[i + 3];
        acc0 += g_hs2[(size_t)s0 * N_CLASSES + c];
        acc1 += g_hs2[(size_t)s1 * N_CLASSES + c];
        acc2 += g_hs2[(size_t)s2 * N_CLASSES + c];
        acc3 += g_hs2[(size_t)s3 * N_CLASSES + c];
    }
    for (; i < e; i++) acc0 += g_hs2[(size_t)g_col[i] * N_CLASSES + c];
    acc0 += acc1 + acc2 + acc3;

    float logit = fmaf(g_dis[n], acc0, b2[c]);
    out[(size_t)n * N_CLASSES + c] = logit;

    float m = logit;
#pragma unroll
    for (int o = 8; o > 0; o >>= 1) m = fmaxf(m, __shfl_xor_sync(0xffffffffu, m, o, 16));
    float ex = expf(logit - m);
    float sum = ex;
#pragma unroll
    for (int o = 8; o > 0; o >>= 1) sum += __shfl_xor_sync(0xffffffffu, sum, o, 16);
    out[(size_t)N_NODES * N_CLASSES + (size_t)n * N_CLASSES + c] = ex / sum;
}

// ---------------- launch ----------------
extern "C" void kernel_launch(void* const* d_in, const int* in_sizes, int n_in,
                              void* d_out, int out_size) {
    const float* X  = (const float*)d_in[0];
    const void*  EI = d_in[1];
    const float* W1 = (const float*)d_in[2];
    const float* B1 = (const float*)d_in[3];
    const float* W2 = (const float*)d_in[4];
    const float* B2 = (const float*)d_in[5];
    float* out = (float*)d_out;

    k_init<<<(N_NODES + 255) / 256, 256>>>((const int*)EI);           // 0
    k_count<<<(N_EDGES + 255) / 256, 256>>>(EI);                       // 1
    k_blocksum<<<N_SCAN_BLOCKS, SCAN_CHUNK>>>();                       // 2
    k_gemm1<<<(N_NODES + BM - 1) / BM, 256>>>(X, W1);                  // 3 (profiled)
    k_scan_bs<<<1, 256>>>();                                           // 4
    k_scan_final<<<N_SCAN_BLOCKS, SCAN_CHUNK>>>();                     // 5
    k_scatter<<<(N_EDGES + 255) / 256, 256>>>(EI);                     // 6
    k_agg1<<<(N_NODES * 32 + 255) / 256, 256>>>(B1);                   // 7
    k_gemm2<<<(N_NODES * N_CLASSES + 255) / 256, 256>>>(W2);           // 8
    k_agg2<<<(N_NODES * 16 + 255) / 256, 256>>>(B2, out);              // 9
}